// round 2
// baseline (speedup 1.0000x reference)
#include <cuda_runtime.h>
#include <cstdint>
#include <math.h>

// Problem constants
#define BB     64
#define D0     4096
#define D1     1024
#define D2OUT  1000
#define TT     32
#define NB     4       // batches per block in the smem-G kernel
#define JT     256     // j-tile (== blockDim.x)

// ---------------- device scratch (static globals; no runtime allocation) ----------------
__device__ float         g_Wt0[(size_t)D0 * D0];   // Wt0[i*D0 + j] = w0[j*D0 + i]
__device__ float         g_Wt2[(size_t)D1 * D1];   // Wt2[i*D1 + j] = w2[j*D1 + i], j<1000 valid (rest stays 0)
__device__ unsigned char g_ns0[BB * D0];           // layer-0 bucket ids n = round(32*x[b, idx0[i]])
__device__ unsigned char g_ns2[BB * D1];           // layer-2 bucket ids
__device__ int           g_cnt0[BB * D0];          // layer-0 spike counts
__device__ unsigned char g_N1[BB * D1];            // layer-1 encoded counts
__device__ int           g_cnt2[BB * D2OUT];       // layer-2 spike counts

// ---------------- uniform spike pattern (matches reference fp32 semantics) ----------------
__device__ __forceinline__ uint32_t pattern_mask(int n) {
    if (n <= 0)  return 0u;
    if (n >= TT) return 0xFFFFFFFFu;
    float spacing = __fdiv_rn(32.0f, (float)n);
    uint32_t m = 0u;
    for (int c = 0; c < TT; c++) {
        double r = fmod((double)c, (double)spacing);
        if (r < 1.0) m |= (1u << c);
    }
    return m;
}

// ---------------- transpose (tiled, padded smem) ----------------
template <int S>
__global__ void transpose_kernel(const float* __restrict__ src) {
    constexpr int rows = (S == 1) ? D0 : D2OUT;   // src rows
    constexpr int cols = (S == 1) ? D0 : D1;      // src cols
    constexpr int ldd  = (S == 1) ? D0 : D1;      // dst row stride
    float* dst = (S == 1) ? g_Wt0 : g_Wt2;

    __shared__ float tile[32][33];
    int c0 = blockIdx.x * 32, r0 = blockIdx.y * 32;
    int cx = c0 + threadIdx.x;
#pragma unroll
    for (int dy = 0; dy < 32; dy += 8) {
        int r = r0 + threadIdx.y + dy;
        if (r < rows && cx < cols)
            tile[threadIdx.y + dy][threadIdx.x] = src[(size_t)r * cols + cx];
    }
    __syncthreads();
    int rx = r0 + threadIdx.x;
#pragma unroll
    for (int dy = 0; dy < 32; dy += 8) {
        int c = c0 + threadIdx.y + dy;
        if (c < cols && rx < rows)
            dst[(size_t)c * ldd + rx] = tile[threadIdx.x][threadIdx.y + dy];
    }
}

// ---------------- bucket-id encodes ----------------
__global__ void encode0_kernel(const float* __restrict__ x, const int* __restrict__ idx0) {
    int b = blockIdx.y;
    int i = blockIdx.x * 256 + threadIdx.x;
    float r = x[b * D0 + idx0[i]];
    g_ns0[b * D0 + i] = (unsigned char)__float2int_rn(r * 32.0f);
}

__global__ void encode2_kernel(const int* __restrict__ idx2) {
    int b = blockIdx.y;
    int i = blockIdx.x * 256 + threadIdx.x;
    g_ns2[b * D1 + i] = g_N1[b * D1 + idx2[i]];
}

// ---------------- main LIF kernel: shared-memory bucket histogram, NB batches per block ---------
// smem layout: G[NB][33][JT] floats, then ns[NB][K] bytes.
template <int S>
__global__ void lif_smem_kernel(const float* __restrict__ thr_p) {
    constexpr int K    = (S == 1) ? D0 : D1;
    constexpr int ldw  = (S == 1) ? D0 : D1;
    constexpr int Jmax = (S == 1) ? D0 : D2OUT;

    extern __shared__ float sm[];
    float* __restrict__ G0 = sm;
    float* __restrict__ G1 = sm + 33 * JT;
    float* __restrict__ G2 = sm + 2 * 33 * JT;
    float* __restrict__ G3 = sm + 3 * 33 * JT;
    unsigned char* ns = (unsigned char*)(sm + NB * 33 * JT);
    __shared__ uint32_t spat[33];

    int tid = threadIdx.x;
    int j0  = blockIdx.x * JT;
    int b0  = blockIdx.y * NB;

    if (tid < 33) spat[tid] = pattern_mask(tid);
    // zero G: each thread zeroes exactly its own (tid mod JT) slots
#pragma unroll
    for (int n = 0; n < 33; n++) {
        G0[n * JT + tid] = 0.f; G1[n * JT + tid] = 0.f;
        G2[n * JT + tid] = 0.f; G3[n * JT + tid] = 0.f;
    }
    // stage bucket ids for NB contiguous batches
    const uint32_t* gns = (const uint32_t*)(((S == 1) ? g_ns0 : g_ns2) + (size_t)b0 * K);
    for (int k = tid; k < NB * K / 4; k += JT) ((uint32_t*)ns)[k] = gns[k];
    __syncthreads();

    const float* W = ((S == 1) ? g_Wt0 : g_Wt2) + j0 + tid;
    const unsigned char* nsp0 = ns;
    const unsigned char* nsp1 = ns + K;
    const unsigned char* nsp2 = ns + 2 * K;
    const unsigned char* nsp3 = ns + 3 * K;

    // software-pipelined main loop: prefetch next group's 4 weights
    float wv0 = W[0 * ldw], wv1 = W[1 * ldw], wv2 = W[2 * ldw], wv3 = W[3 * ldw];
#pragma unroll 1
    for (int i = 0; i < K; i += 4) {
        float p0 = wv0, p1 = wv1, p2 = wv2, p3 = wv3;
        int ip = (i + 4 < K) ? (i + 4) : 0;   // wrap prefetch (extra reads of group 0 are harmless)
        wv0 = W[(ip + 0) * ldw];
        wv1 = W[(ip + 1) * ldw];
        wv2 = W[(ip + 2) * ldw];
        wv3 = W[(ip + 3) * ldw];
        uint32_t m0 = *(const uint32_t*)(nsp0 + i);
        uint32_t m1 = *(const uint32_t*)(nsp1 + i);
        uint32_t m2 = *(const uint32_t*)(nsp2 + i);
        uint32_t m3 = *(const uint32_t*)(nsp3 + i);
#pragma unroll
        for (int u = 0; u < 4; u++) {
            float w = (u == 0) ? p0 : (u == 1) ? p1 : (u == 2) ? p2 : p3;
            int sh = 8 * u;
            G0[(int)((m0 >> sh) & 0xffu) * JT + tid] += w;
            G1[(int)((m1 >> sh) & 0xffu) * JT + tid] += w;
            G2[(int)((m2 >> sh) & 0xffu) * JT + tid] += w;
            G3[(int)((m3 >> sh) & 0xffu) * JT + tid] += w;
        }
    }
    // no sync needed: each thread reads only its own G slots below

    float thr = *thr_p;
    int j = j0 + tid;
    bool valid = (j < Jmax);
    int* cnt_out = (S == 1) ? g_cnt0 : g_cnt2;

#pragma unroll 1
    for (int b = 0; b < NB; b++) {
        const float* Gb = sm + b * 33 * JT;
        float I[TT];
#pragma unroll
        for (int t = 0; t < TT; t++) I[t] = 0.f;
        // buckets ascending n (n=0 pattern is all-zero; its G is unused)
#pragma unroll 1
        for (int n = 1; n < 33; n++) {
            float acc = Gb[n * JT + tid];
            uint32_t m = spat[n];
#pragma unroll
            for (int t = 0; t < TT; t++)
                if ((m >> t) & 1u) I[t] += acc;
        }
        float memb = 0.f;
        int cnt = 0;
#pragma unroll
        for (int t = 0; t < TT; t++) {
            memb += I[t];
            if (memb > thr) { memb -= thr; cnt++; }
        }
        if (valid) cnt_out[(size_t)(b0 + b) * Jmax + j] = cnt;
    }
}

// ---------------- pooling + layer-1 re-encoding (exact integer/pow2 arithmetic) ----------------
__global__ void mid_kernel(const int* __restrict__ idx1) {
    int b = blockIdx.x, p = threadIdx.x;   // p in [0,1024)
    int ch = p >> 4, oh = (p >> 2) & 3, ow = p & 3;
    int c = 0;
#pragma unroll
    for (int dh = 0; dh < 2; dh++)
#pragma unroll
        for (int dw = 0; dw < 2; dw++) {
            int k = ch * 64 + (2 * oh + dh) * 8 + (2 * ow + dw);
            c += g_cnt0[b * D0 + idx1[k]];
        }
    // y_rate*32 == c/4 exactly; round half-to-even matches jnp.round
    g_N1[b * D1 + p] = (unsigned char)__float2int_rn((float)c * 0.25f);
}

// ---------------- output gather (spike counts as float) ----------------
__global__ void out_kernel(const int* __restrict__ idx_out, float* __restrict__ out) {
    int b = blockIdx.x, j = threadIdx.x;
    if (j < D2OUT) out[b * D2OUT + j] = (float)g_cnt2[b * D2OUT + idx_out[j]];
}

// ---------------- launch ----------------
extern "C" void kernel_launch(void* const* d_in, const int* in_sizes, int n_in,
                              void* d_out, int out_size) {
    (void)in_sizes; (void)n_in; (void)out_size;
    const float* x       = (const float*)d_in[0];
    const float* w0      = (const float*)d_in[1];
    const float* t0      = (const float*)d_in[2];
    const float* w2      = (const float*)d_in[3];
    const float* t2      = (const float*)d_in[4];
    const int*   idx0    = (const int*)d_in[5];
    const int*   idx1    = (const int*)d_in[6];
    const int*   idx2    = (const int*)d_in[7];
    const int*   idx_out = (const int*)d_in[8];
    float* out = (float*)d_out;

    const int SMEM1 = NB * 33 * JT * 4 + NB * D0;   // 135168 + 16384 = 151552
    const int SMEM2 = NB * 33 * JT * 4 + NB * D1;   // 135168 +  4096 = 139264
    cudaFuncSetAttribute(lif_smem_kernel<1>, cudaFuncAttributeMaxDynamicSharedMemorySize, SMEM1);
    cudaFuncSetAttribute(lif_smem_kernel<2>, cudaFuncAttributeMaxDynamicSharedMemorySize, SMEM2);

    dim3 tb(32, 8);
    transpose_kernel<1><<<dim3(D0 / 32, D0 / 32), tb>>>(w0);
    transpose_kernel<2><<<dim3(D1 / 32, (D2OUT + 31) / 32), tb>>>(w2);

    encode0_kernel<<<dim3(D0 / 256, BB), 256>>>(x, idx0);
    lif_smem_kernel<1><<<dim3(D0 / JT, BB / NB), JT, SMEM1>>>(t0);

    mid_kernel<<<BB, D1>>>(idx1);
    encode2_kernel<<<dim3(D1 / 256, BB), 256>>>(idx2);
    lif_smem_kernel<2><<<dim3((D2OUT + JT - 1) / JT, BB / NB), JT, SMEM2>>>(t2);

    out_kernel<<<BB, 1024>>>(idx_out, out);
}